// round 5
// baseline (speedup 1.0000x reference)
#include <cuda_runtime.h>
#include <cuda_bf16.h>

// y[m] = 0.75 * sum_k( x[m,k] * wcs[k] ),  wcs[k] = sum_n weight[n,k]
// x: [M,K] fp32, weight: [N,K] fp32, out: [M,1] fp32.  M=K=N=8192.
// HBM-streaming: 512 MiB compulsory traffic.
//
// Fully stateless 3-kernel pipeline (no atomics, no init, no replay state):
//  1) colsum_part: 512 blocks, each OVERWRITES its float4 partial sum into
//     g_part[chunk][k] (plain stores).
//  2) reduce_wcs: tiny kernel, wcs[k] = sum_c g_part[c][k] (2 MB L2-resident).
//  3) rowdot: 512 blocks x 256 thr, 2 rows per warp -> wcs loaded once per
//     row-pair (1.5 loads per x-float4 instead of 2), doubled x MLP.

#define MM 8192
#define KK 8192
#define NN 8192
#define COL4 (KK / 4)        // 2048 float4 per row

// ------------------------------------------------- phase 1: partial colsums
#define CS_THREADS 256
#define CHUNKS 64
#define ROWS_PER_CHUNK (NN / CHUNKS)      // 128

__device__ float4 g_part[CHUNKS][COL4];   // 2 MB partial sums (overwritten)
__device__ float  g_wcs[KK];              // reduced column sums (overwritten)

__global__ __launch_bounds__(CS_THREADS) void colsum_part_kernel(const float* __restrict__ weight) {
    const int col4 = blockIdx.x * CS_THREADS + threadIdx.x;   // 0..2047
    const int row0 = blockIdx.y * ROWS_PER_CHUNK;

    const float4* __restrict__ p =
        reinterpret_cast<const float4*>(weight) + (size_t)row0 * COL4 + col4;

    float4 acc = make_float4(0.f, 0.f, 0.f, 0.f);
#pragma unroll 8
    for (int r = 0; r < ROWS_PER_CHUNK; ++r) {
        float4 v = __ldcs(p + (size_t)r * COL4);
        acc.x += v.x; acc.y += v.y; acc.z += v.z; acc.w += v.w;
    }
    g_part[blockIdx.y][col4] = acc;   // plain store, no atomic, no init needed
}

// ------------------------------------------------- phase 2: reduce partials
#define RED_THREADS 256

__global__ __launch_bounds__(RED_THREADS) void reduce_wcs_kernel() {
    const int col4 = blockIdx.x * RED_THREADS + threadIdx.x;  // 0..2047
    float4 acc = make_float4(0.f, 0.f, 0.f, 0.f);
#pragma unroll 8
    for (int c = 0; c < CHUNKS; ++c) {
        float4 v = g_part[c][col4];
        acc.x += v.x; acc.y += v.y; acc.z += v.z; acc.w += v.w;
    }
    reinterpret_cast<float4*>(g_wcs)[col4] = acc;
}

// ------------------------------------------------- phase 3: row dots
// 512 blocks x 256 thr (8 warps). Warp w handles rows bx*16 + 2w and +1.
#define DOT_THREADS 256

__global__ __launch_bounds__(DOT_THREADS) void rowdot_kernel(const float* __restrict__ x,
                                                             float* __restrict__ out) {
    const int wid  = threadIdx.x >> 5;
    const int lane = threadIdx.x & 31;
    const int r0 = blockIdx.x * 16 + wid * 2;
    const int r1 = r0 + 1;

    const float4* __restrict__ x0 = reinterpret_cast<const float4*>(x) + (size_t)r0 * COL4;
    const float4* __restrict__ x1 = reinterpret_cast<const float4*>(x) + (size_t)r1 * COL4;
    const float4* __restrict__ w4 = reinterpret_cast<const float4*>(g_wcs);

    float acc0 = 0.f, acc1 = 0.f;
#pragma unroll 4
    for (int i = lane; i < COL4; i += 32) {
        float4 wv = w4[i];                 // L1/L2-resident (cached, reused)
        float4 a  = __ldcs(x0 + i);        // streaming, evict-first
        float4 b  = __ldcs(x1 + i);
        acc0 = fmaf(a.x, wv.x, acc0);
        acc0 = fmaf(a.y, wv.y, acc0);
        acc0 = fmaf(a.z, wv.z, acc0);
        acc0 = fmaf(a.w, wv.w, acc0);
        acc1 = fmaf(b.x, wv.x, acc1);
        acc1 = fmaf(b.y, wv.y, acc1);
        acc1 = fmaf(b.z, wv.z, acc1);
        acc1 = fmaf(b.w, wv.w, acc1);
    }

#pragma unroll
    for (int off = 16; off > 0; off >>= 1) {
        acc0 += __shfl_down_sync(0xFFFFFFFFu, acc0, off);
        acc1 += __shfl_down_sync(0xFFFFFFFFu, acc1, off);
    }
    if (lane == 0) {
        out[r0] = 0.75f * acc0;
        out[r1] = 0.75f * acc1;
    }
}

// ---------------------------------------------------------------- launcher
extern "C" void kernel_launch(void* const* d_in, const int* in_sizes, int n_in,
                              void* d_out, int out_size) {
    const float* x      = (const float*)d_in[0];
    const float* weight = (const float*)d_in[1];
    float* out = (float*)d_out;

    dim3 cs_grid(COL4 / CS_THREADS, CHUNKS);          // (8, 64)
    colsum_part_kernel<<<cs_grid, CS_THREADS>>>(weight);

    reduce_wcs_kernel<<<COL4 / RED_THREADS, RED_THREADS>>>();  // 8 blocks

    rowdot_kernel<<<MM / 16, DOT_THREADS>>>(x, out);  // 512 blocks
}

// round 6
// speedup vs baseline: 1.0577x; 1.0577x over previous
#include <cuda_runtime.h>
#include <cuda_bf16.h>

// y[m] = 0.75 * sum_k( x[m,k] * wcs[k] ),  wcs[k] = sum_n weight[n,k]
// x: [M,K] fp32, weight: [N,K] fp32, out: [M,1] fp32.  M=K=N=8192.
// HBM-streaming: 512 MiB compulsory traffic.
//
// Pipeline:
//  0) cudaMemsetAsync zeroes g_wcs (graph memset node, cheaper than a kernel)
//  1) colsum: 2048 blocks x 256 thr (fine-grained for tail balance),
//     32 rows per thread, 4 atomicAdds into g_wcs (256-way fan-in, negligible)
//  2) rowdot: 8192 blocks x 256 thr, one block per output row (measured-best
//     streaming shape: occ 94%, ~7 TB/s on the x stream)

#define MM 8192
#define KK 8192
#define NN 8192
#define COL4 (KK / 4)   // 2048 float4 per row

__device__ float g_wcs[KK];

// ------------------------------------------------- column sum of weight[N,K]
#define CS_THREADS 256
#define CHUNKS 256
#define ROWS_PER_CHUNK (NN / CHUNKS)   // 32

__global__ __launch_bounds__(CS_THREADS) void colsum_kernel(const float* __restrict__ weight) {
    const int col4 = blockIdx.x * CS_THREADS + threadIdx.x;   // 0..2047
    const int row0 = blockIdx.y * ROWS_PER_CHUNK;

    const float4* __restrict__ p =
        reinterpret_cast<const float4*>(weight) + (size_t)row0 * COL4 + col4;

    float4 acc = make_float4(0.f, 0.f, 0.f, 0.f);
#pragma unroll 8
    for (int r = 0; r < ROWS_PER_CHUNK; ++r) {
        float4 v = p[(size_t)r * COL4];
        acc.x += v.x; acc.y += v.y; acc.z += v.z; acc.w += v.w;
    }

    const int col = col4 * 4;
    atomicAdd(&g_wcs[col + 0], acc.x);
    atomicAdd(&g_wcs[col + 1], acc.y);
    atomicAdd(&g_wcs[col + 2], acc.z);
    atomicAdd(&g_wcs[col + 3], acc.w);
}

// ------------------------------------------------- per-row dot with g_wcs
#define DOT_THREADS 256

__global__ __launch_bounds__(DOT_THREADS) void rowdot_kernel(const float* __restrict__ x,
                                                             float* __restrict__ out) {
    const int row = blockIdx.x;
    const float4* __restrict__ x4 = reinterpret_cast<const float4*>(x) + (size_t)row * COL4;
    const float4* __restrict__ w4 = reinterpret_cast<const float4*>(g_wcs);

    float acc = 0.0f;
#pragma unroll
    for (int i = 0; i < COL4 / DOT_THREADS; ++i) {   // 8 iterations
        const int idx = i * DOT_THREADS + threadIdx.x;
        float4 xv = x4[idx];
        float4 wv = w4[idx];
        acc = fmaf(xv.x, wv.x, acc);
        acc = fmaf(xv.y, wv.y, acc);
        acc = fmaf(xv.z, wv.z, acc);
        acc = fmaf(xv.w, wv.w, acc);
    }

    // warp reduce
#pragma unroll
    for (int off = 16; off > 0; off >>= 1)
        acc += __shfl_down_sync(0xFFFFFFFFu, acc, off);

    __shared__ float warp_sums[DOT_THREADS / 32];
    const int lane = threadIdx.x & 31;
    const int wid  = threadIdx.x >> 5;
    if (lane == 0) warp_sums[wid] = acc;
    __syncthreads();

    if (wid == 0) {
        float s = (lane < DOT_THREADS / 32) ? warp_sums[lane] : 0.0f;
#pragma unroll
        for (int off = 4; off > 0; off >>= 1)
            s += __shfl_down_sync(0xFFFFFFFFu, s, off);
        if (lane == 0) out[row] = 0.75f * s;
    }
}

// ---------------------------------------------------------------- launcher
extern "C" void kernel_launch(void* const* d_in, const int* in_sizes, int n_in,
                              void* d_out, int out_size) {
    const float* x      = (const float*)d_in[0];
    const float* weight = (const float*)d_in[1];
    float* out = (float*)d_out;

    void* wcs_ptr = nullptr;
    cudaGetSymbolAddress(&wcs_ptr, g_wcs);
    cudaMemsetAsync(wcs_ptr, 0, KK * sizeof(float));   // graph memset node

    dim3 cs_grid(COL4 / CS_THREADS, CHUNKS);   // (8, 256) = 2048 blocks
    colsum_kernel<<<cs_grid, CS_THREADS>>>(weight);

    rowdot_kernel<<<MM, DOT_THREADS>>>(x, out);
}

// round 7
// speedup vs baseline: 1.1333x; 1.0715x over previous
#include <cuda_runtime.h>
#include <cuda_bf16.h>

// y[m] = 0.75 * sum_k( x[m,k] * wcs[k] ),  wcs[k] = sum_n weight[n,k]
// x: [M,K] fp32, weight: [N,K] fp32, out: [M,1] fp32.  M=K=N=8192.
// HBM-streaming: 512 MiB compulsory traffic. Fully stateless, no atomics.
//
//  1) colsum_part: 512 blocks x 256 thr; each thread sums 128 rows of one
//     float4 column and OVERWRITES g_part[chunk][col] (proven 43.1us shape).
//  2) reduce_wcs: 32 blocks x 256 thr; one scalar column per thread,
//     64 strided-coalesced partial reads (2 MB, L2-resident, ~2us).
//  3) rowdot2: 4096 blocks x 256 thr; TWO rows per block so each wcs load
//     feeds two accumulators (1.5 loads per x-float4 instead of 2).

#define MM 8192
#define KK 8192
#define NN 8192
#define COL4 (KK / 4)        // 2048 float4 per row

// ------------------------------------------------- phase 1: partial colsums
#define CS_THREADS 256
#define CHUNKS 64
#define ROWS_PER_CHUNK (NN / CHUNKS)      // 128

__device__ float g_part[CHUNKS][KK];      // 2 MB partials (overwritten)
__device__ float g_wcs[KK];               // reduced sums (overwritten)

__global__ __launch_bounds__(CS_THREADS) void colsum_part_kernel(const float* __restrict__ weight) {
    const int col4 = blockIdx.x * CS_THREADS + threadIdx.x;   // 0..2047
    const int row0 = blockIdx.y * ROWS_PER_CHUNK;

    const float4* __restrict__ p =
        reinterpret_cast<const float4*>(weight) + (size_t)row0 * COL4 + col4;

    float4 acc = make_float4(0.f, 0.f, 0.f, 0.f);
#pragma unroll 8
    for (int r = 0; r < ROWS_PER_CHUNK; ++r) {
        float4 v = __ldcs(p + (size_t)r * COL4);
        acc.x += v.x; acc.y += v.y; acc.z += v.z; acc.w += v.w;
    }
    reinterpret_cast<float4*>(g_part[blockIdx.y])[col4] = acc;
}

// ------------------------------------------------- phase 2: reduce partials
#define RED_THREADS 256
#define RED_BLOCKS (KK / RED_THREADS)     // 32

__global__ __launch_bounds__(RED_THREADS) void reduce_wcs_kernel() {
    const int col = blockIdx.x * RED_THREADS + threadIdx.x;   // 0..8191
    float acc = 0.f;
#pragma unroll 8
    for (int c = 0; c < CHUNKS; ++c)
        acc += g_part[c][col];
    g_wcs[col] = acc;
}

// ------------------------------------------------- phase 3: row dots (2/block)
#define DOT_THREADS 256

__global__ __launch_bounds__(DOT_THREADS) void rowdot2_kernel(const float* __restrict__ x,
                                                              float* __restrict__ out) {
    const int r0 = blockIdx.x * 2;
    const int r1 = r0 + 1;
    const float4* __restrict__ x0 = reinterpret_cast<const float4*>(x) + (size_t)r0 * COL4;
    const float4* __restrict__ x1 = reinterpret_cast<const float4*>(x) + (size_t)r1 * COL4;
    const float4* __restrict__ w4 = reinterpret_cast<const float4*>(g_wcs);

    float acc0 = 0.f, acc1 = 0.f;
#pragma unroll
    for (int i = 0; i < COL4 / DOT_THREADS; ++i) {   // 8 iterations
        const int idx = i * DOT_THREADS + threadIdx.x;
        float4 wv = w4[idx];           // shared between both rows
        float4 a  = __ldcs(x0 + idx);  // streaming, evict-first
        float4 b  = __ldcs(x1 + idx);
        acc0 = fmaf(a.x, wv.x, acc0);
        acc0 = fmaf(a.y, wv.y, acc0);
        acc0 = fmaf(a.z, wv.z, acc0);
        acc0 = fmaf(a.w, wv.w, acc0);
        acc1 = fmaf(b.x, wv.x, acc1);
        acc1 = fmaf(b.y, wv.y, acc1);
        acc1 = fmaf(b.z, wv.z, acc1);
        acc1 = fmaf(b.w, wv.w, acc1);
    }

    // warp reduce both accumulators
#pragma unroll
    for (int off = 16; off > 0; off >>= 1) {
        acc0 += __shfl_down_sync(0xFFFFFFFFu, acc0, off);
        acc1 += __shfl_down_sync(0xFFFFFFFFu, acc1, off);
    }

    __shared__ float ws0[DOT_THREADS / 32];
    __shared__ float ws1[DOT_THREADS / 32];
    const int lane = threadIdx.x & 31;
    const int wid  = threadIdx.x >> 5;
    if (lane == 0) { ws0[wid] = acc0; ws1[wid] = acc1; }
    __syncthreads();

    if (wid == 0) {
        float s0 = (lane < DOT_THREADS / 32) ? ws0[lane] : 0.0f;
        float s1 = (lane < DOT_THREADS / 32) ? ws1[lane] : 0.0f;
#pragma unroll
        for (int off = 4; off > 0; off >>= 1) {
            s0 += __shfl_down_sync(0xFFFFFFFFu, s0, off);
            s1 += __shfl_down_sync(0xFFFFFFFFu, s1, off);
        }
        if (lane == 0) {
            out[r0] = 0.75f * s0;
            out[r1] = 0.75f * s1;
        }
    }
}

// ---------------------------------------------------------------- launcher
extern "C" void kernel_launch(void* const* d_in, const int* in_sizes, int n_in,
                              void* d_out, int out_size) {
    const float* x      = (const float*)d_in[0];
    const float* weight = (const float*)d_in[1];
    float* out = (float*)d_out;

    dim3 cs_grid(COL4 / CS_THREADS, CHUNKS);            // (8, 64) = 512 blocks
    colsum_part_kernel<<<cs_grid, CS_THREADS>>>(weight);

    reduce_wcs_kernel<<<RED_BLOCKS, RED_THREADS>>>();   // 32 blocks

    rowdot2_kernel<<<MM / 2, DOT_THREADS>>>(x, out);    // 4096 blocks
}

// round 8
// speedup vs baseline: 1.1851x; 1.0457x over previous
#include <cuda_runtime.h>
#include <cuda_bf16.h>

// y[m] = 0.75 * sum_k( x[m,k] * wcs[k] ),  wcs[k] = sum_n weight[n,k]
// x: [M,K] fp32, weight: [N,K] fp32, out: [M,1] fp32.  M=K=N=8192.
// HBM-streaming: 512 MiB compulsory traffic.
//
// Pipeline (each phase in its measured-best shape):
//  0) cudaMemsetAsync zeroes g_wcs (graph memset node, ~1us)
//  1) colsum: grid (8 x 74) = 592 blocks = EXACTLY 4 CTAs/SM -> no wave
//     quantization tail (512-block version wasted 13% on 4-vs-3 imbalance).
//     Each thread sums ~110 rows of one float4 column, 4 atomicAdds
//     (74-way fan-in per address — proven cheap at 64-way in the 84.5us build).
//  2) rowdot: 8192 blocks x 256 thr, one block per row (measured-best, occ 94%).

#define MM 8192
#define KK 8192
#define NN 8192
#define COL4 (KK / 4)   // 2048 float4 per row

__device__ float g_wcs[KK];

// ------------------------------------------------- column sum of weight[N,K]
#define CS_THREADS 256
#define CHUNKS 74        // 8 col-tiles x 74 chunks = 592 blocks = 4 per SM

__global__ __launch_bounds__(CS_THREADS) void colsum_kernel(const float* __restrict__ weight) {
    const int col4 = blockIdx.x * CS_THREADS + threadIdx.x;       // 0..2047
    const int r0 = (int)(((long long)blockIdx.y * NN) / CHUNKS);  // chunk row range
    const int r1 = (int)(((long long)(blockIdx.y + 1) * NN) / CHUNKS);

    const float4* __restrict__ w4 = reinterpret_cast<const float4*>(weight) + col4;

    float4 acc = make_float4(0.f, 0.f, 0.f, 0.f);
#pragma unroll 4
    for (int r = r0; r < r1; ++r) {
        float4 v = __ldcs(w4 + (size_t)r * COL4);
        acc.x += v.x; acc.y += v.y; acc.z += v.z; acc.w += v.w;
    }

    const int col = col4 * 4;
    atomicAdd(&g_wcs[col + 0], acc.x);
    atomicAdd(&g_wcs[col + 1], acc.y);
    atomicAdd(&g_wcs[col + 2], acc.z);
    atomicAdd(&g_wcs[col + 3], acc.w);
}

// ------------------------------------------------- per-row dot with g_wcs
#define DOT_THREADS 256

__global__ __launch_bounds__(DOT_THREADS) void rowdot_kernel(const float* __restrict__ x,
                                                             float* __restrict__ out) {
    const int row = blockIdx.x;
    const float4* __restrict__ x4 = reinterpret_cast<const float4*>(x) + (size_t)row * COL4;
    const float4* __restrict__ w4 = reinterpret_cast<const float4*>(g_wcs);

    float acc = 0.0f;
#pragma unroll
    for (int i = 0; i < COL4 / DOT_THREADS; ++i) {   // 8 iterations
        const int idx = i * DOT_THREADS + threadIdx.x;
        float4 xv = x4[idx];
        float4 wv = w4[idx];
        acc = fmaf(xv.x, wv.x, acc);
        acc = fmaf(xv.y, wv.y, acc);
        acc = fmaf(xv.z, wv.z, acc);
        acc = fmaf(xv.w, wv.w, acc);
    }

    // warp reduce
#pragma unroll
    for (int off = 16; off > 0; off >>= 1)
        acc += __shfl_down_sync(0xFFFFFFFFu, acc, off);

    __shared__ float warp_sums[DOT_THREADS / 32];
    const int lane = threadIdx.x & 31;
    const int wid  = threadIdx.x >> 5;
    if (lane == 0) warp_sums[wid] = acc;
    __syncthreads();

    if (wid == 0) {
        float s = (lane < DOT_THREADS / 32) ? warp_sums[lane] : 0.0f;
#pragma unroll
        for (int off = 4; off > 0; off >>= 1)
            s += __shfl_down_sync(0xFFFFFFFFu, s, off);
        if (lane == 0) out[row] = 0.75f * s;
    }
}

// ---------------------------------------------------------------- launcher
extern "C" void kernel_launch(void* const* d_in, const int* in_sizes, int n_in,
                              void* d_out, int out_size) {
    const float* x      = (const float*)d_in[0];
    const float* weight = (const float*)d_in[1];
    float* out = (float*)d_out;

    void* wcs_ptr = nullptr;
    cudaGetSymbolAddress(&wcs_ptr, g_wcs);
    cudaMemsetAsync(wcs_ptr, 0, KK * sizeof(float));   // graph memset node

    dim3 cs_grid(COL4 / CS_THREADS, CHUNKS);           // (8, 74) = 592 blocks
    colsum_kernel<<<cs_grid, CS_THREADS>>>(weight);

    rowdot_kernel<<<MM, DOT_THREADS>>>(x, out);
}

// round 9
// speedup vs baseline: 1.1887x; 1.0030x over previous
#include <cuda_runtime.h>
#include <cuda_bf16.h>

// y[m] = 0.75 * sum_k( x[m,k] * wcs[k] ),  wcs[k] = sum_n weight[n,k]
// x: [M,K] fp32, weight: [N,K] fp32, out: [M,1] fp32.  M=K=N=8192.
// HBM-streaming: 512 MiB compulsory traffic.
//
// Pipeline:
//  0) cudaMemsetAsync zeroes g_wcs (graph memset node, ~1us)
//  1) colsum: float2 per thread -> 303104 threads = 64 warps/SM (occ ~100%),
//     grid (16 x 74) = 1184 blocks = 8 CTAs/SM. Atomic fan-in stays 74 per
//     address (proven cheap; 256-way was the R6 disaster). 2x bytes in flight
//     vs the float4/32-warp version that stalled at 41.6% occupancy.
//  2) rowdot: 8192 blocks x 256 thr, one block per row (measured-best shape).

#define MM 8192
#define KK 8192
#define NN 8192
#define COL4 (KK / 4)   // 2048 float4 per row
#define COL2 (KK / 2)   // 4096 float2 per row

__device__ float g_wcs[KK];

// ------------------------------------------------- column sum of weight[N,K]
#define CS_THREADS 256
#define CHUNKS 74        // atomic fan-in per address = 74

__global__ __launch_bounds__(CS_THREADS) void colsum_kernel(const float* __restrict__ weight) {
    const int col2 = blockIdx.x * CS_THREADS + threadIdx.x;       // 0..4095
    const int r0 = (int)(((long long)blockIdx.y * NN) / CHUNKS);  // ~110 rows/chunk
    const int r1 = (int)(((long long)(blockIdx.y + 1) * NN) / CHUNKS);

    const float2* __restrict__ w2 = reinterpret_cast<const float2*>(weight) + col2;

    float2 acc = make_float2(0.f, 0.f);
#pragma unroll 8
    for (int r = r0; r < r1; ++r) {
        float2 v = __ldcs(w2 + (size_t)r * COL2);
        acc.x += v.x; acc.y += v.y;
    }

    const int col = col2 * 2;
    atomicAdd(&g_wcs[col + 0], acc.x);
    atomicAdd(&g_wcs[col + 1], acc.y);
}

// ------------------------------------------------- per-row dot with g_wcs
#define DOT_THREADS 256

__global__ __launch_bounds__(DOT_THREADS) void rowdot_kernel(const float* __restrict__ x,
                                                             float* __restrict__ out) {
    const int row = blockIdx.x;
    const float4* __restrict__ x4 = reinterpret_cast<const float4*>(x) + (size_t)row * COL4;
    const float4* __restrict__ w4 = reinterpret_cast<const float4*>(g_wcs);

    float acc = 0.0f;
#pragma unroll
    for (int i = 0; i < COL4 / DOT_THREADS; ++i) {   // 8 iterations
        const int idx = i * DOT_THREADS + threadIdx.x;
        float4 xv = x4[idx];
        float4 wv = w4[idx];
        acc = fmaf(xv.x, wv.x, acc);
        acc = fmaf(xv.y, wv.y, acc);
        acc = fmaf(xv.z, wv.z, acc);
        acc = fmaf(xv.w, wv.w, acc);
    }

    // warp reduce
#pragma unroll
    for (int off = 16; off > 0; off >>= 1)
        acc += __shfl_down_sync(0xFFFFFFFFu, acc, off);

    __shared__ float warp_sums[DOT_THREADS / 32];
    const int lane = threadIdx.x & 31;
    const int wid  = threadIdx.x >> 5;
    if (lane == 0) warp_sums[wid] = acc;
    __syncthreads();

    if (wid == 0) {
        float s = (lane < DOT_THREADS / 32) ? warp_sums[lane] : 0.0f;
#pragma unroll
        for (int off = 4; off > 0; off >>= 1)
            s += __shfl_down_sync(0xFFFFFFFFu, s, off);
        if (lane == 0) out[row] = 0.75f * s;
    }
}

// ---------------------------------------------------------------- launcher
extern "C" void kernel_launch(void* const* d_in, const int* in_sizes, int n_in,
                              void* d_out, int out_size) {
    const float* x      = (const float*)d_in[0];
    const float* weight = (const float*)d_in[1];
    float* out = (float*)d_out;

    void* wcs_ptr = nullptr;
    cudaGetSymbolAddress(&wcs_ptr, g_wcs);
    cudaMemsetAsync(wcs_ptr, 0, KK * sizeof(float));   // graph memset node

    dim3 cs_grid(COL2 / CS_THREADS, CHUNKS);           // (16, 74) = 1184 blocks
    colsum_kernel<<<cs_grid, CS_THREADS>>>(weight);

    rowdot_kernel<<<MM, DOT_THREADS>>>(x, out);
}